// round 3
// baseline (speedup 1.0000x reference)
#include <cuda_runtime.h>
#include <cstdint>

#define B_   4
#define H_   8
#define LQ   1024
#define DH   64
#define KL   1024
#define NJ   33      // 2*MAX_REL_POS + 1
#define NJP  36      // padded stride for S
#define MAXREL 16

// Scratch: S[b][h][q][j] with j-stride NJP. 4*8*1024*36 floats = 4.7MB.
__device__ float g_S[B_ * H_ * LQ * NJP];

// ---------------------------------------------------------------------------
// Kernel 1: S[b,h,q,j] = sum_d query[b,h,q,d] * rel_table[j,d]
// grid (LQ/128, H, B), block (9, 32) = 288 threads.
// Each thread computes a 4q x 4j register tile (j padded to 36).
// ---------------------------------------------------------------------------
__global__ void __launch_bounds__(288) compute_s_kernel(
    const float* __restrict__ query,
    const float* __restrict__ table)
{
    __shared__ float qS[128][DH + 1];   // +1 pad: conflict-free scalar column reads
    __shared__ float tT[DH][NJP];       // transposed table, j-contiguous

    const int tid   = threadIdx.y * 9 + threadIdx.x;
    const int qBase = blockIdx.x * 128;
    const int h     = blockIdx.y;
    const int b     = blockIdx.z;

    const float* qptr = query + (size_t)(((b * H_ + h) * LQ) + qBase) * DH;

    // Load 128x64 query tile (float4 global loads, scalar smem stores)
    for (int i = tid; i < 128 * DH / 4; i += 288) {
        float4 v = ((const float4*)qptr)[i];
        int qr = i >> 4;
        int d0 = (i & 15) << 2;
        qS[qr][d0 + 0] = v.x; qS[qr][d0 + 1] = v.y;
        qS[qr][d0 + 2] = v.z; qS[qr][d0 + 3] = v.w;
    }
    // Load 33x64 table, transposed into tT[d][j]
    for (int i = tid; i < NJ * DH / 4; i += 288) {
        float4 v = ((const float4*)table)[i];
        int j  = i >> 4;
        int d0 = (i & 15) << 2;
        tT[d0 + 0][j] = v.x; tT[d0 + 1][j] = v.y;
        tT[d0 + 2][j] = v.z; tT[d0 + 3][j] = v.w;
    }
    // Zero pad columns j = 33..35
    for (int i = tid; i < DH * 3; i += 288) tT[i / 3][NJ + (i % 3)] = 0.f;
    __syncthreads();

    const int jg = threadIdx.x;       // 0..8  -> j tile of 4
    const int qg = threadIdx.y;       // 0..31 -> q tile of 4
    const int q0 = qg * 4;
    const int j0 = jg * 4;

    float acc[4][4] = {};
    #pragma unroll 8
    for (int d = 0; d < DH; d++) {
        float4 tv = *(const float4*)(&tT[d][j0]);
        float t0 = tv.x, t1 = tv.y, t2 = tv.z, t3 = tv.w;
        #pragma unroll
        for (int i = 0; i < 4; i++) {
            float qv = qS[q0 + i][d];
            acc[i][0] += qv * t0;
            acc[i][1] += qv * t1;
            acc[i][2] += qv * t2;
            acc[i][3] += qv * t3;
        }
    }

    float* sp = g_S + (size_t)(((b * H_ + h) << 10) + qBase + q0) * NJP + j0;
    #pragma unroll
    for (int i = 0; i < 4; i++) {
        float4 o = make_float4(acc[i][0], acc[i][1], acc[i][2], acc[i][3]);
        *(float4*)(sp + i * NJP) = o;
    }
}

// ---------------------------------------------------------------------------
// Kernel 2: out[b,h,q,k] = S[b,h,q, clip(ts[b,k]-ts[b,q],-16,16)+16]
// grid (LQ, B), block 256. Each thread handles 4 consecutive k for all 8 h.
// ---------------------------------------------------------------------------
__global__ void __launch_bounds__(256) gather_kernel(
    const int* __restrict__ time_ids,
    float* __restrict__ out)
{
    __shared__ float s_sm[H_][NJ];

    const int q   = blockIdx.x;
    const int b   = blockIdx.y;
    const int tid = threadIdx.x;

    // H_*NJ = 264 > 256 threads: MUST stride this loop.
    for (int i = tid; i < H_ * NJ; i += 256) {
        int h = i / NJ;
        int j = i - h * NJ;
        s_sm[h][j] = g_S[(size_t)(((b * H_ + h) << 10) + q) * NJP + j];
    }

    const int* tsb = time_ids + b * KL;
    const int  tq  = tsb[q];
    __syncthreads();

    const int k0 = tid * 4;
    int4 tk = *(const int4*)(tsb + k0);

    int i0 = min(max(tk.x - tq, -MAXREL), MAXREL) + MAXREL;
    int i1 = min(max(tk.y - tq, -MAXREL), MAXREL) + MAXREL;
    int i2 = min(max(tk.z - tq, -MAXREL), MAXREL) + MAXREL;
    int i3 = min(max(tk.w - tq, -MAXREL), MAXREL) + MAXREL;

    float* op = out + ((size_t)(b * H_ * LQ + q) << 10) + k0;
    #pragma unroll
    for (int h = 0; h < H_; h++) {
        float4 o = make_float4(s_sm[h][i0], s_sm[h][i1], s_sm[h][i2], s_sm[h][i3]);
        *(float4*)(op + ((size_t)h << 20)) = o;
    }
}

// ---------------------------------------------------------------------------
extern "C" void kernel_launch(void* const* d_in, const int* in_sizes, int n_in,
                              void* d_out, int out_size)
{
    const float* query    = (const float*)d_in[0];   // [4,8,1024,64]
    const float* table    = (const float*)d_in[1];   // [33,64]
    const int*   time_ids = (const int*)d_in[2];     // [4,1024] int32
    float*       out      = (float*)d_out;           // [4,8,1024,1024]

    dim3 g1(LQ / 128, H_, B_);
    dim3 b1(9, 32, 1);
    compute_s_kernel<<<g1, b1>>>(query, table);

    dim3 g2(LQ, B_);
    gather_kernel<<<g2, 256>>>(time_ids, out);
}